// round 13
// baseline (speedup 1.0000x reference)
#include <cuda_runtime.h>

// DisturbanceRegressionLoss2Heads — two-kernel pure-stream split.
// K1: stream out0 -> per-pixel changepoint + OLS coeffs into device scratch.
// K2: stream out1 + scratch -> squared-error reduction -> scalar loss.
// out: (8, 2, 30, 256, 256) fp32; target unused; output: scalar fp32 loss.

static constexpr int YT   = 30;
static constexpr int HWC  = 256 * 256;            // 65536
static constexpr int B    = 8;
static constexpr int NPIX = B * HWC;              // 524288
static constexpr int VEC  = 4;                    // pixels per thread (float4)
static constexpr int TPB  = 128;
static constexpr int NBLK = NPIX / VEC / TPB;     // 1024
static constexpr int NG   = NPIX / VEC;           // 131072 float4-groups

// static scratch (no allocation): 4x 2MB coeff planes (SoA float4) + packed d
__device__ float4       g_scb4[NG];
__device__ float4       g_icb4[NG];
__device__ float4       g_sca4[NG];
__device__ float4       g_ica4[NG];
__device__ unsigned     g_d4[NG];

__device__ double       g_acc = 0.0;
__device__ unsigned int g_cnt = 0;

// ---------------- K1: out0 scan -> coefficients ----------------
__global__ __launch_bounds__(TPB)
void k1_fit(const float* __restrict__ outp) {
    const int g   = blockIdx.x * TPB + threadIdx.x;   // float4-group id
    const int b   = g >> 14;                          // g / (HWC/4)
    const int hw4 = g & 16383;

    const float4* p0 = reinterpret_cast<const float4*>(
                           outp + (size_t)b * (2 * YT * HWC)) + hw4;  // out[:,0]

    float prev[VEC], mn[VEC], py[VEC], pty[VEC], SyB[VEC], StyB[VEC];
    int   d[VEC];
#pragma unroll
    for (int l = 0; l < VEC; ++l) {
        mn[l] = -7.0f; d[l] = 0;
        py[l] = 0.f; pty[l] = 0.f; SyB[l] = 0.f; StyB[l] = 0.f;
        prev[l] = 0.f;
    }

#pragma unroll
    for (int t = 0; t < YT; ++t) {
        float4 v4 = __ldg(p0 + (size_t)t * (HWC / 4));
        float v[VEC] = {v4.x, v4.y, v4.z, v4.w};
#pragma unroll
        for (int l = 0; l < VEC; ++l) {
            if (t >= 2 && t < YT - 1) {               // diff index 2..28
                float dv = v[l] - prev[l];
                if (dv < mn[l]) {                     // first-occurrence min
                    mn[l] = dv; d[l] = t;
                    SyB[l] = py[l]; StyB[l] = pty[l]; // prefix over t' < d
                }
            }
            prev[l] = v[l];
            py[l]  += v[l];
            pty[l]  = fmaf((float)t, v[l], pty[l]);
        }
    }

    float scb[VEC], icb[VEC], sca[VEC], ica[VEC];
#pragma unroll
    for (int l = 0; l < VEC; ++l) {
        const float nb = (float)d[l];
        const float na = (float)(YT - d[l]);          // >= 2

        // before-segment (may be empty: all sums 0 -> slope 0, icpt 0)
        float nsb  = fmaxf(nb, 1.f);
        float mxb  = 0.5f * nb * (nb - 1.f) / nsb;    // Sx / n_safe
        float myb  = SyB[l] / nsb;
        float covb = StyB[l] - mxb * SyB[l];
        float varb = nb * (nb * nb - 1.f) * (1.f / 12.f);
        float slb  = (varb > 0.f) ? covb / fmaxf(varb, 1.f) : 0.f;
        scb[l]     = fminf(fmaxf(slb, 0.f), 2.f);
        icb[l]     = fminf(fmaxf(myb - slb * mxb, 0.f), 100.f);

        // after-segment via total - prefix (x = t - d)
        float SyA  = py[l]  - SyB[l];
        float SxyA = (pty[l] - StyB[l]) - nb * SyA;
        float mxa  = 0.5f * (na - 1.f);
        float mya  = SyA / na;
        float cova = SxyA - mxa * SyA;
        float vara = na * (na * na - 1.f) * (1.f / 12.f);
        float sla  = cova / fmaxf(vara, 1.f);         // na>=2 -> var>0
        sca[l]     = fminf(fmaxf(sla, 0.f), 2.f);
        ica[l]     = fminf(fmaxf(mya - sla * mxa, 0.f), 100.f);
    }

    g_scb4[g] = make_float4(scb[0], scb[1], scb[2], scb[3]);
    g_icb4[g] = make_float4(icb[0], icb[1], icb[2], icb[3]);
    g_sca4[g] = make_float4(sca[0], sca[1], sca[2], sca[3]);
    g_ica4[g] = make_float4(ica[0], ica[1], ica[2], ica[3]);
    g_d4[g]   = (unsigned)d[0] | ((unsigned)d[1] << 8)
              | ((unsigned)d[2] << 16) | ((unsigned)d[3] << 24);
}

// ---------------- K2: out1 stream -> loss ----------------
__global__ __launch_bounds__(TPB)
void k2_loss(const float* __restrict__ outp, float* __restrict__ res) {
    const int g   = blockIdx.x * TPB + threadIdx.x;   // float4-group id
    const int b   = g >> 14;
    const int hw4 = g & 16383;

    const float4* p1 = reinterpret_cast<const float4*>(
                           outp + (size_t)b * (2 * YT * HWC))
                       + (size_t)YT * (HWC / 4) + hw4;                // out[:,1]

    const float4 scb4 = g_scb4[g];
    const float4 icb4 = g_icb4[g];
    const float4 sca4 = g_sca4[g];
    const float4 ica4 = g_ica4[g];
    const unsigned dw = g_d4[g];

    const float scb[VEC] = {scb4.x, scb4.y, scb4.z, scb4.w};
    const float icb[VEC] = {icb4.x, icb4.y, icb4.z, icb4.w};
    const float sca[VEC] = {sca4.x, sca4.y, sca4.z, sca4.w};
    const float ica[VEC] = {ica4.x, ica4.y, ica4.z, ica4.w};
    const int   d[VEC]   = {(int)(dw & 0xFF), (int)((dw >> 8) & 0xFF),
                            (int)((dw >> 16) & 0xFF), (int)(dw >> 24)};

    float acc = 0.f;
#pragma unroll
    for (int t = 0; t < YT; ++t) {
        float4 y4 = __ldg(p1 + (size_t)t * (HWC / 4));
        float y[VEC] = {y4.x, y4.y, y4.z, y4.w};
#pragma unroll
        for (int l = 0; l < VEC; ++l) {
            float f = (t < d[l]) ? fmaf(scb[l], (float)t, icb[l])
                                 : fmaf(sca[l], (float)(t - d[l]), ica[l]);
            float r = f - y[l];
            acc = fmaf(r, r, acc);
        }
    }

    // block reduction: warp shuffle -> shared -> one double atomic
#pragma unroll
    for (int o = 16; o > 0; o >>= 1) acc += __shfl_xor_sync(0xffffffffu, acc, o);
    __shared__ float sm[TPB / 32];
    const int wid  = threadIdx.x >> 5;
    const int lane = threadIdx.x & 31;
    if (lane == 0) sm[wid] = acc;
    __syncthreads();
    if (wid == 0) {
        float s = (lane < TPB / 32) ? sm[lane] : 0.f;
#pragma unroll
        for (int o = (TPB / 32) >> 1; o > 0; o >>= 1)
            s += __shfl_xor_sync(0xffffffffu, s, o);
        if (lane == 0) {
            atomicAdd(&g_acc, (double)s);
            __threadfence();
            unsigned t = atomicInc(&g_cnt, NBLK - 1);   // wraps to 0 on last
            if (t == (unsigned)(NBLK - 1)) {
                double tot = atomicAdd(&g_acc, 0.0);    // coherent read
                *res = (float)(tot * (1.0 / ((double)YT * (double)NPIX)));
                atomicExch(reinterpret_cast<unsigned long long*>(&g_acc), 0ULL);
            }
        }
    }
}

extern "C" void kernel_launch(void* const* d_in, const int* in_sizes, int n_in,
                              void* d_out, int out_size) {
    (void)in_sizes; (void)n_in; (void)out_size;
    const float* outp = (const float*)d_in[0];      // 'out' per metadata order
    float*       res  = (float*)d_out;
    k1_fit<<<NBLK, TPB>>>(outp);
    k2_loss<<<NBLK, TPB>>>(outp, res);
}

// round 14
// speedup vs baseline: 1.1634x; 1.1634x over previous
#include <cuda_runtime.h>

// DisturbanceRegressionLoss2Heads — two-pass prefix-capture, VEC=4 (R2 baseline),
// with streaming (evict-first) loads: data is strictly single-use.
// out: (8, 2, 30, 256, 256) fp32; target unused; output: scalar fp32 loss.

static constexpr int YT   = 30;
static constexpr int HWC  = 256 * 256;            // 65536
static constexpr int B    = 8;
static constexpr int NPIX = B * HWC;              // 524288
static constexpr int VEC  = 4;                    // pixels per thread (float4)
static constexpr int TPB  = 256;
static constexpr int NBLK = NPIX / VEC / TPB;     // 512

__device__ double       g_acc = 0.0;
__device__ unsigned int g_cnt = 0;

__global__ __launch_bounds__(TPB)
void disturbance_loss_kernel(const float* __restrict__ outp,
                             float* __restrict__ res) {
    const int g   = blockIdx.x * TPB + threadIdx.x;   // float4-group id
    const int b   = g >> 14;                          // g / (HWC/4)
    const int hw4 = g & 16383;

    const float4* p0 = reinterpret_cast<const float4*>(
                           outp + (size_t)b * (2 * YT * HWC)) + hw4;  // out[:,0]
    const float4* p1 = p0 + (size_t)YT * (HWC / 4);                   // out[:,1]

    // ---- pass 1 over out0: argmin with prefix-sum capture ----
    float prev[VEC], mn[VEC], py[VEC], pty[VEC], SyB[VEC], StyB[VEC];
    int   d[VEC];
#pragma unroll
    for (int l = 0; l < VEC; ++l) {
        mn[l] = -7.0f; d[l] = 0;
        py[l] = 0.f; pty[l] = 0.f; SyB[l] = 0.f; StyB[l] = 0.f;
        prev[l] = 0.f;
    }

#pragma unroll
    for (int t = 0; t < YT; ++t) {
        float4 v4 = __ldcs(p0 + (size_t)t * (HWC / 4));   // evict-first stream
        float v[VEC] = {v4.x, v4.y, v4.z, v4.w};
#pragma unroll
        for (int l = 0; l < VEC; ++l) {
            if (t >= 2 && t < YT - 1) {               // diff index 2..28
                float dv = v[l] - prev[l];
                if (dv < mn[l]) {                     // first-occurrence min
                    mn[l] = dv; d[l] = t;
                    SyB[l] = py[l]; StyB[l] = pty[l]; // prefix over t' < d
                }
            }
            prev[l] = v[l];
            py[l]  += v[l];
            pty[l]  = fmaf((float)t, v[l], pty[l]);
        }
    }

    // ---- per-pixel OLS coefficients (registers only) ----
    float scb[VEC], icb[VEC], sca[VEC], ica[VEC];
#pragma unroll
    for (int l = 0; l < VEC; ++l) {
        const float nb = (float)d[l];
        const float na = (float)(YT - d[l]);          // >= 2

        // before-segment (may be empty: all sums 0 -> slope 0, icpt 0)
        float nsb  = fmaxf(nb, 1.f);
        float mxb  = 0.5f * nb * (nb - 1.f) / nsb;    // Sx / n_safe
        float myb  = SyB[l] / nsb;
        float covb = StyB[l] - mxb * SyB[l];
        float varb = nb * (nb * nb - 1.f) * (1.f / 12.f);
        float slb  = (varb > 0.f) ? covb / fmaxf(varb, 1.f) : 0.f;
        scb[l]     = fminf(fmaxf(slb, 0.f), 2.f);
        icb[l]     = fminf(fmaxf(myb - slb * mxb, 0.f), 100.f);

        // after-segment via total - prefix (x = t - d)
        float SyA  = py[l]  - SyB[l];
        float SxyA = (pty[l] - StyB[l]) - nb * SyA;
        float mxa  = 0.5f * (na - 1.f);
        float mya  = SyA / na;
        float cova = SxyA - mxa * SyA;
        float vara = na * (na * na - 1.f) * (1.f / 12.f);
        float sla  = cova / fmaxf(vara, 1.f);         // na>=2 -> var>0
        sca[l]     = fminf(fmaxf(sla, 0.f), 2.f);
        ica[l]     = fminf(fmaxf(mya - sla * mxa, 0.f), 100.f);
    }

    // ---- pass 2 over out1: squared error of piecewise fit ----
    float acc = 0.f;
#pragma unroll
    for (int t = 0; t < YT; ++t) {
        float4 y4 = __ldcs(p1 + (size_t)t * (HWC / 4));   // evict-first stream
        float y[VEC] = {y4.x, y4.y, y4.z, y4.w};
#pragma unroll
        for (int l = 0; l < VEC; ++l) {
            float f = (t < d[l]) ? fmaf(scb[l], (float)t, icb[l])
                                 : fmaf(sca[l], (float)(t - d[l]), ica[l]);
            float r = f - y[l];
            acc = fmaf(r, r, acc);
        }
    }

    // ---- block reduction: warp shuffle -> shared -> one double atomic ----
#pragma unroll
    for (int o = 16; o > 0; o >>= 1) acc += __shfl_xor_sync(0xffffffffu, acc, o);
    __shared__ float sm[TPB / 32];
    const int wid  = threadIdx.x >> 5;
    const int lane = threadIdx.x & 31;
    if (lane == 0) sm[wid] = acc;
    __syncthreads();
    if (wid == 0) {
        float s = (lane < TPB / 32) ? sm[lane] : 0.f;
#pragma unroll
        for (int o = (TPB / 32) >> 1; o > 0; o >>= 1)
            s += __shfl_xor_sync(0xffffffffu, s, o);
        if (lane == 0) {
            atomicAdd(&g_acc, (double)s);
            __threadfence();
            unsigned t = atomicInc(&g_cnt, NBLK - 1);   // wraps to 0 on last
            if (t == (unsigned)(NBLK - 1)) {
                double tot = atomicAdd(&g_acc, 0.0);    // coherent read
                *res = (float)(tot * (1.0 / ((double)YT * (double)NPIX)));
                atomicExch(reinterpret_cast<unsigned long long*>(&g_acc), 0ULL);
            }
        }
    }
}

extern "C" void kernel_launch(void* const* d_in, const int* in_sizes, int n_in,
                              void* d_out, int out_size) {
    (void)in_sizes; (void)n_in; (void)out_size;
    const float* outp = (const float*)d_in[0];      // 'out' per metadata order
    float*       res  = (float*)d_out;
    disturbance_loss_kernel<<<NBLK, TPB>>>(outp, res);
}